// round 7
// baseline (speedup 1.0000x reference)
#include <cuda_runtime.h>
#include <cuda_fp16.h>
#include <math.h>
#include <stdint.h>

#define NB 8
#define NN 8192
#define DD 256
#define NSPLIT 16
#define NCH 64

__device__ float d_Spart[NSPLIT * NB * DD * DD];
__device__ float d_S[NB * DD * DD];
__device__ float d_T1[NB * DD * DD];
__device__ float d_P[NB * DD * DD];
__device__ __half d_Mth[NB * DD * DD];
__device__ __half d_Mtl[NB * DD * DD];
__device__ __half d_kh[NB * NN * DD];
__device__ __half d_kl[NB * NN * DD];
__device__ __half d_vh[NB * NN * DD];
__device__ __half d_vl[NB * NN * DD];
__device__ __half d_qh[NB * NN * DD];
__device__ __half d_ql[NB * NN * DD];
__device__ float d_Upart[NCH * NB * DD];
__device__ float d_Wpart[NCH * NB * DD];
__device__ float d_Cpart[NCH * NB];
__device__ float d_u[NB * DD];
__device__ float d_w[NB * DD];
__device__ float d_cc[NB];
__device__ float d_kv1[NB * DD];
__device__ float d_kv2[NB * DD];
__device__ float d_r[NB * DD];
__device__ int   g_mask_mode;

// ---------------- helpers ----------------
__global__ void detect_mask_kernel(const unsigned int* __restrict__ mw) {
    __shared__ int hasByte;
    if (threadIdx.x == 0) hasByte = 0;
    __syncthreads();
    int local = 0;
    for (int i = threadIdx.x; i < 16384; i += blockDim.x) {
        unsigned v = mw[i];
        if (v > 1u && v != 0x3F800000u) local = 1;
    }
    if (local) atomicOr(&hasByte, 1);
    __syncthreads();
    if (threadIdx.x == 0) g_mask_mode = hasByte ? 1 : 0;
}
__device__ __forceinline__ int mask_raw(const void* m, long i, int mode) {
    return (mode == 0) ? (((const unsigned int*)m)[i] != 0u)
                       : (((const unsigned char*)m)[i] != 0);
}
__device__ __forceinline__ void cpa16(void* s, const void* g) {
    unsigned sa = (unsigned)__cvta_generic_to_shared(s);
    asm volatile("cp.async.cg.shared.global [%0], [%1], 16;" :: "r"(sa), "l"(g));
}
#define CPA_COMMIT() asm volatile("cp.async.commit_group;" ::: "memory")
#define CPA_WAIT(n)  asm volatile("cp.async.wait_group %0;" :: "n"(n) : "memory")

__device__ __forceinline__ uint32_t smem_u32(const void* p) {
    uint32_t a;
    asm("{ .reg .u64 t; cvta.to.shared.u64 t, %1; cvt.u32.u64 %0, t; }"
        : "=r"(a) : "l"(p));
    return a;
}
__device__ __forceinline__ void mma16816(float* c, const uint32_t* a, const uint32_t* b) {
    asm volatile("mma.sync.aligned.m16n8k16.row.col.f32.f16.f16.f32 "
        "{%0,%1,%2,%3}, {%4,%5,%6,%7}, {%8,%9}, {%0,%1,%2,%3};"
        : "+f"(c[0]), "+f"(c[1]), "+f"(c[2]), "+f"(c[3])
        : "r"(a[0]), "r"(a[1]), "r"(a[2]), "r"(a[3]), "r"(b[0]), "r"(b[1]));
}
__device__ __forceinline__ void ldsm4(uint32_t* r, uint32_t a) {
    asm volatile("ldmatrix.sync.aligned.m8n8.x4.shared.b16 {%0,%1,%2,%3}, [%4];"
        : "=r"(r[0]), "=r"(r[1]), "=r"(r[2]), "=r"(r[3]) : "r"(a));
}
__device__ __forceinline__ void ldsm4t(uint32_t* r, uint32_t a) {
    asm volatile("ldmatrix.sync.aligned.m8n8.x4.trans.shared.b16 {%0,%1,%2,%3}, [%4];"
        : "=r"(r[0]), "=r"(r[1]), "=r"(r[2]), "=r"(r[3]) : "r"(a));
}
// split pair -> half2 hi + half2 lo (hi = 10-bit-truncated, exact in fp16)
__device__ __forceinline__ void splitm(float x0, float x1, uint32_t& h, uint32_t& l) {
    float h0 = __uint_as_float(__float_as_uint(x0) & 0xFFFFE000u);
    float h1 = __uint_as_float(__float_as_uint(x1) & 0xFFFFE000u);
    __half2 hh = __floats2half2_rn(h0, h1);
    __half2 ll = __floats2half2_rn(x0 - h0, x1 - h1);
    h = *(uint32_t*)&hh;
    l = *(uint32_t*)&ll;
}

// ---------------- convert: fp32 -> fp16 hi/lo + masked colsums -------------
__global__ __launch_bounds__(256) void convert_kernel(
    const float* __restrict__ query, const float* __restrict__ key,
    const float* __restrict__ value, const void* __restrict__ mask)
{
    __shared__ float redu[8][260];
    __shared__ float redw[8][260];
    __shared__ float cred[8];
    int bc = blockIdx.x;
    int b = bc >> 6, ch = bc & 63;
    long nbase = (long)b * NN + ch * 128;
    int t = threadIdx.x, rg = t >> 5, c0 = (t & 31) * 8;
    int mode = g_mask_mode;
    float su[8], sw[8];
    #pragma unroll
    for (int j = 0; j < 8; j++) { su[j] = 0.f; sw[j] = 0.f; }
    float cnt = 0.f;

    for (int i = 0; i < 16; i++) {
        int row = rg * 16 + i;
        long n = nbase + row;
        float mm = mask_raw(mask, n, mode) ? 0.f : 1.f;
        long g = n * DD + c0;
        float4 ka = *(const float4*)(key + g),   kb2 = *(const float4*)(key + g + 4);
        float4 va = *(const float4*)(value + g), vb2 = *(const float4*)(value + g + 4);
        float4 qa = *(const float4*)(query + g), qb2 = *(const float4*)(query + g + 4);
        ka.x *= mm; ka.y *= mm; ka.z *= mm; ka.w *= mm;
        kb2.x *= mm; kb2.y *= mm; kb2.z *= mm; kb2.w *= mm;
        su[0] += ka.x;  su[1] += ka.y;  su[2] += ka.z;  su[3] += ka.w;
        su[4] += kb2.x; su[5] += kb2.y; su[6] += kb2.z; su[7] += kb2.w;
        sw[0] = fmaf(mm, va.x, sw[0]);  sw[1] = fmaf(mm, va.y, sw[1]);
        sw[2] = fmaf(mm, va.z, sw[2]);  sw[3] = fmaf(mm, va.w, sw[3]);
        sw[4] = fmaf(mm, vb2.x, sw[4]); sw[5] = fmaf(mm, vb2.y, sw[5]);
        sw[6] = fmaf(mm, vb2.z, sw[6]); sw[7] = fmaf(mm, vb2.w, sw[7]);
        uint4 h, l;
        splitm(ka.x, ka.y, h.x, l.x);   splitm(ka.z, ka.w, h.y, l.y);
        splitm(kb2.x, kb2.y, h.z, l.z); splitm(kb2.z, kb2.w, h.w, l.w);
        *(uint4*)(d_kh + g) = h; *(uint4*)(d_kl + g) = l;
        splitm(va.x, va.y, h.x, l.x);   splitm(va.z, va.w, h.y, l.y);
        splitm(vb2.x, vb2.y, h.z, l.z); splitm(vb2.z, vb2.w, h.w, l.w);
        *(uint4*)(d_vh + g) = h; *(uint4*)(d_vl + g) = l;
        splitm(qa.x, qa.y, h.x, l.x);   splitm(qa.z, qa.w, h.y, l.y);
        splitm(qb2.x, qb2.y, h.z, l.z); splitm(qb2.z, qb2.w, h.w, l.w);
        *(uint4*)(d_qh + g) = h; *(uint4*)(d_ql + g) = l;
        cnt += mm;
    }
    #pragma unroll
    for (int j = 0; j < 8; j++) { redu[rg][c0 + j] = su[j]; redw[rg][c0 + j] = sw[j]; }
    if ((t & 31) == 0) cred[rg] = cnt;
    __syncthreads();
    float s1 = 0.f, s2 = 0.f;
    #pragma unroll
    for (int r2 = 0; r2 < 8; r2++) { s1 += redu[r2][t]; s2 += redw[r2][t]; }
    d_Upart[(ch * NB + b) * DD + t] = s1;
    d_Wpart[(ch * NB + b) * DD + t] = s2;
    if (t == 0) {
        float c = 0.f;
        #pragma unroll
        for (int r2 = 0; r2 < 8; r2++) c += cred[r2];
        d_Cpart[ch * NB + b] = c;
    }
}

// ---------------- stage 1: S = kh/kl^T @ vh/vl  (ldmatrix.trans + mma) -----
// CTA 128d x 128e, n-chunk 512, stage = 32 n, 2-stage cp.async pipeline.
// smem stage: AH(8K) AL(8K) BH(8K) BL(8K); row n: n*256 + ((u^(n&7))<<4), u 0..15.
#define S1_STG 32768
__global__ __launch_bounds__(256, 2) void stage1_kernel() {
    extern __shared__ char sm1[];
    uint32_t sb = smem_u32(sm1);
    int t = threadIdx.x, lane = t & 31, wid = t >> 5;
    int b = blockIdx.z >> 4, sp = blockIdx.z & 15;
    int d0 = blockIdx.x * 128, e0 = blockIdx.y * 128;
    long nbase = (long)b * NN + (long)sp * 512;
    int wn = wid & 3, we = wid >> 2;
    int grp = lane >> 3, li = lane & 7;
    int g = lane >> 2, tg = lane & 3;

    int cn = t >> 4, cu = t & 15;          // copy mapping: 16 thr/row
    auto issue = [&](int s_idx, int buf) {
        #pragma unroll
        for (int j = 0; j < 2; j++) {
            int n = cn + j * 16;
            long gofs = (nbase + s_idx * 32 + n) * (long)DD;
            char* dst = sm1 + buf * S1_STG + n * 256 + (((cu) ^ (n & 7)) << 4);
            cpa16(dst,          d_kh + gofs + d0 + cu * 8);
            cpa16(dst + 8192,   d_kl + gofs + d0 + cu * 8);
            cpa16(dst + 16384,  d_vh + gofs + e0 + cu * 8);
            cpa16(dst + 24576,  d_vl + gofs + e0 + cu * 8);
        }
        CPA_COMMIT();
    };

    float acc[2][8][4];
    #pragma unroll
    for (int mi = 0; mi < 2; mi++)
        #pragma unroll
        for (int ni = 0; ni < 8; ni++)
            #pragma unroll
            for (int j = 0; j < 4; j++) acc[mi][ni][j] = 0.f;

    issue(0, 0);
    for (int s = 0; s < 16; s++) {
        if (s + 1 < 16) { issue(s + 1, (s + 1) & 1); CPA_WAIT(1); }
        else CPA_WAIT(0);
        __syncthreads();
        uint32_t base = sb + (s & 1) * S1_STG;
        #pragma unroll
        for (int ks = 0; ks < 2; ks++) {
            int kb = ks * 16;
            int nA = kb + ((grp >> 1) << 3) + li;     // A-trans rows
            int nB = kb + ((grp & 1) << 3) + li;      // B-trans rows
            uint32_t aH[2][4], aL[2][4];
            #pragma unroll
            for (int mi = 0; mi < 2; mi++) {
                int uA = wn * 4 + mi * 2 + (grp & 1);
                uint32_t ad = base + nA * 256 + ((uA ^ (nA & 7)) << 4);
                ldsm4t(aH[mi], ad);
                ldsm4t(aL[mi], ad + 8192);
            }
            #pragma unroll
            for (int nf = 0; nf < 4; nf++) {
                int uB = we * 8 + nf * 2 + (grp >> 1);
                uint32_t bd = base + 16384 + nB * 256 + ((uB ^ (nB & 7)) << 4);
                uint32_t bh4[4], bl4[4];
                ldsm4t(bh4, bd);
                ldsm4t(bl4, bd + 8192);
                uint32_t bh0[2] = {bh4[0], bh4[1]}, bh1[2] = {bh4[2], bh4[3]};
                uint32_t bl0[2] = {bl4[0], bl4[1]}, bl1[2] = {bl4[2], bl4[3]};
                #pragma unroll
                for (int mi = 0; mi < 2; mi++) {
                    mma16816(acc[mi][nf * 2], aH[mi], bh0);
                    mma16816(acc[mi][nf * 2], aH[mi], bl0);
                    mma16816(acc[mi][nf * 2], aL[mi], bh0);
                    mma16816(acc[mi][nf * 2 + 1], aH[mi], bh1);
                    mma16816(acc[mi][nf * 2 + 1], aH[mi], bl1);
                    mma16816(acc[mi][nf * 2 + 1], aL[mi], bh1);
                }
            }
        }
        __syncthreads();
    }

    float* outp = d_Spart + ((long)(sp * NB + b) << 16);
    #pragma unroll
    for (int mi = 0; mi < 2; mi++) {
        int d = d0 + wn * 32 + mi * 16 + g;
        #pragma unroll
        for (int ni = 0; ni < 8; ni++) {
            int e = e0 + we * 64 + ni * 8 + 2 * tg;
            float2 v;
            v.x = acc[mi][ni][0]; v.y = acc[mi][ni][1];
            *(float2*)&outp[(long)d * DD + e] = v;
            v.x = acc[mi][ni][2]; v.y = acc[mi][ni][3];
            *(float2*)&outp[(long)(d + 8) * DD + e] = v;
        }
    }
}

__global__ void s_reduce_kernel() {
    long i = (long)blockIdx.x * 256 + threadIdx.x;
    int b = (int)(i >> 16);
    int j = (int)(i & 65535);
    float s = 0.f;
    #pragma unroll
    for (int sp = 0; sp < NSPLIT; sp++)
        s += d_Spart[((long)(sp * NB + b) << 16) + j];
    d_S[((long)b << 16) + j] = s;
}

__global__ void uvw_reduce_kernel() {
    int b = blockIdx.x, d = threadIdx.x;
    float su = 0.f, sw = 0.f;
    for (int sp = 0; sp < NCH; sp++) {
        su += d_Upart[(sp * NB + b) * DD + d];
        sw += d_Wpart[(sp * NB + b) * DD + d];
    }
    d_u[b * DD + d] = su;
    d_w[b * DD + d] = sw;
    if (d == 0) {
        float c = 0.f;
        for (int sp = 0; sp < NCH; sp++) c += d_Cpart[sp * NB + b];
        d_cc[b] = c;
    }
}

__global__ void kv_kernel(const float* __restrict__ Wk,
                          const float* __restrict__ Wv,
                          const float* __restrict__ bv) {
    int b = blockIdx.x, d = threadIdx.x;
    __shared__ float su[DD], sw[DD];
    su[d] = d_u[b * DD + d];
    sw[d] = d_w[b * DD + d];
    __syncthreads();
    float s1 = 0.f, s2 = 0.f;
    for (int i = 0; i < DD; i++) {
        s1 = fmaf(Wk[(long)d * DD + i], su[i], s1);
        s2 = fmaf(Wv[(long)d * DD + i], sw[i], s2);
    }
    d_kv1[b * DD + d] = s1;
    d_kv2[b * DD + d] = s2 + d_cc[b] * bv[d];
}

// ---------------- small batched GEMM ----------------
template<bool TA, bool TB, bool EPI, bool SPL>
__global__ __launch_bounds__(128) void sgemm_k(
    const float* __restrict__ A, long sA,
    const float* __restrict__ B, long sB,
    float* __restrict__ C, __half* __restrict__ Ch, __half* __restrict__ Cl,
    const float* __restrict__ x1, int sx1,
    const float* __restrict__ y1, int sy1,
    const float* __restrict__ x2, int sx2,
    const float* __restrict__ y2, int sy2,
    float scale)
{
    __shared__ float As[16][36];
    __shared__ float Bs[16][68];
    int t = threadIdx.x;
    int b = blockIdx.z;
    int d0 = blockIdx.x * 32, e0 = blockIdx.y * 64;
    const float* Ab = A + (long)b * sA;
    const float* Bb = B + (long)b * sB;
    int td = t & 7, te = t >> 3;

    float acc[4][4];
    #pragma unroll
    for (int r = 0; r < 4; r++)
        #pragma unroll
        for (int c = 0; c < 4; c++) acc[r][c] = 0.f;

    for (int kt = 0; kt < DD; kt += 16) {
        if (TA) {
            int row = t >> 3, col = (t & 7) * 4;
            *(float4*)&As[row][col] = *(const float4*)&Ab[(long)(kt + row) * DD + d0 + col];
        } else {
            int row = t >> 2, col = (t & 3) * 4;
            float4 v = *(const float4*)&Ab[(long)(d0 + row) * DD + kt + col];
            As[col + 0][row] = v.x; As[col + 1][row] = v.y;
            As[col + 2][row] = v.z; As[col + 3][row] = v.w;
        }
        #pragma unroll
        for (int h = 0; h < 2; h++) {
            int idx = t * 4 + h * 512;
            if (TB) {
                int row = idx >> 4, col = idx & 15;
                float4 v = *(const float4*)&Bb[(long)(e0 + row) * DD + kt + col];
                Bs[col + 0][row] = v.x; Bs[col + 1][row] = v.y;
                Bs[col + 2][row] = v.z; Bs[col + 3][row] = v.w;
            } else {
                int row = idx >> 6, col = idx & 63;
                *(float4*)&Bs[row][col] = *(const float4*)&Bb[(long)(kt + row) * DD + e0 + col];
            }
        }
        __syncthreads();
        #pragma unroll
        for (int k = 0; k < 16; k++) {
            float4 a = *(const float4*)&As[k][td * 4];
            float4 bb = *(const float4*)&Bs[k][te * 4];
            float av[4] = {a.x, a.y, a.z, a.w};
            float bv2[4] = {bb.x, bb.y, bb.z, bb.w};
            #pragma unroll
            for (int r = 0; r < 4; r++)
                #pragma unroll
                for (int c = 0; c < 4; c++)
                    acc[r][c] = fmaf(av[r], bv2[c], acc[r][c]);
        }
        __syncthreads();
    }

    #pragma unroll
    for (int r = 0; r < 4; r++) {
        int d = d0 + td * 4 + r;
        #pragma unroll
        for (int c = 0; c < 4; c++) {
            int e = e0 + te * 4 + c;
            float v = acc[r][c];
            if (EPI)
                v = (v + x1[b * sx1 + d] * y1[b * sy1 + e]
                       + x2[b * sx2 + d] * y2[b * sy2 + e]) * scale;
            long offo = ((long)b << 16) + (long)d * DD + e;
            if (SPL) {
                float hf = __uint_as_float(__float_as_uint(v) & 0xFFFFE000u);
                Ch[offo] = __float2half_rn(hf);
                Cl[offo] = __float2half_rn(v - hf);
            } else {
                C[offo] = v;
            }
        }
    }
}

// ---------------- softmax / rvec ----------------
__global__ void softmax_kernel() {
    int b = blockIdx.x, ec = blockIdx.y;
    int tx = threadIdx.x, ty = threadIdx.y;
    float* Pb = d_P + ((long)b << 16);
    int e = ec * 64 + tx;
    __shared__ float red[4][64];

    float mx = -3.4e38f;
    for (int d = ty; d < DD; d += 4) mx = fmaxf(mx, Pb[(long)d * DD + e]);
    red[ty][tx] = mx;
    __syncthreads();
    mx = fmaxf(fmaxf(red[0][tx], red[1][tx]), fmaxf(red[2][tx], red[3][tx]));
    __syncthreads();
    float s = 0.f;
    for (int d = ty; d < DD; d += 4) {
        float ev = expf(Pb[(long)d * DD + e] - mx);
        Pb[(long)d * DD + e] = ev;
        s += ev;
    }
    red[ty][tx] = s;
    __syncthreads();
    float inv = 1.0f / (red[0][tx] + red[1][tx] + red[2][tx] + red[3][tx]);
    for (int d = ty; d < DD; d += 4) Pb[(long)d * DD + e] *= inv;
}

__global__ void rvec_kernel(const float* __restrict__ bq) {
    int b = blockIdx.x, e = threadIdx.x;
    const float* Pb = d_P + ((long)b << 16);
    float s = 0.f;
    for (int d = 0; d < DD; d++) s = fmaf(bq[d], Pb[(long)d * DD + e], s);
    d_r[b * DD + e] = s;
}

// ---------------- stage 3: out = q @ M + r (ldmatrix + mma) ----------------
// CTA 128n x 128e, K=256 in 4 chunks of 64, double-buffered.
// smem stage: AH(16K) AL(16K) BH(16K) BL(16K); row r: r*128 + ((u^(r&7))<<4), u 0..7.
#define S3_STG 65536
__global__ __launch_bounds__(256, 1) void stage3_kernel(
    float* __restrict__ out)
{
    extern __shared__ char sm3[];
    __shared__ float rsh[DD];
    uint32_t sb = smem_u32(sm3);
    int t = threadIdx.x, lane = t & 31, wid = t >> 5;
    int b = blockIdx.z;
    long n0 = (long)blockIdx.x * 128;
    int e0 = blockIdx.y * 128;
    long boff = (long)b << 16;
    if (t < DD) rsh[t] = d_r[b * DD + t];

    int wn = wid & 3, we = wid >> 2;
    int grp = lane >> 3, li = lane & 7;
    int g = lane >> 2, tg = lane & 3;

    int cr = t >> 1, cu2 = (t & 1) * 4;     // copy mapping: 2 thr/row, 4 units each
    auto issue = [&](int c, int buf) {
        #pragma unroll
        for (int j = 0; j < 2; j++) {
            int r = cr + j * 0;   // cr covers 0..127 with 2 thr each
            (void)r;
        }
        #pragma unroll
        for (int u = 0; u < 4; u++) {
            int uu = cu2 + u;
            char* dst = sm3 + buf * S3_STG + cr * 128 + ((uu ^ (cr & 7)) << 4);
            long ga = ((long)b * NN + n0 + cr) * DD + c * 64 + uu * 8;
            long gb = boff + (long)(e0 + cr) * DD + c * 64 + uu * 8;
            cpa16(dst,          d_qh + ga);
            cpa16(dst + 16384,  d_ql + ga);
            cpa16(dst + 32768,  d_Mth + gb);
            cpa16(dst + 49152,  d_Mtl + gb);
        }
        CPA_COMMIT();
    };

    float acc[2][8][4];
    #pragma unroll
    for (int mi = 0; mi < 2; mi++)
        #pragma unroll
        for (int ni = 0; ni < 8; ni++)
            #pragma unroll
            for (int j = 0; j < 4; j++) acc[mi][ni][j] = 0.f;

    issue(0, 0);
    for (int c = 0; c < 4; c++) {
        if (c + 1 < 4) { issue(c + 1, (c + 1) & 1); CPA_WAIT(1); }
        else CPA_WAIT(0);
        __syncthreads();
        uint32_t base = sb + (c & 1) * S3_STG;
        #pragma unroll
        for (int ks = 0; ks < 4; ks++) {
            int u0 = ks * 2;
            uint32_t aH[2][4], aL[2][4];
            #pragma unroll
            for (int mi = 0; mi < 2; mi++) {
                int n = wn * 32 + mi * 16 + ((grp & 1) << 3) + li;
                int u = u0 + (grp >> 1);
                uint32_t ad = base + n * 128 + ((u ^ (n & 7)) << 4);
                ldsm4(aH[mi], ad);
                ldsm4(aL[mi], ad + 16384);
            }
            #pragma unroll
            for (int nf = 0; nf < 4; nf++) {
                int e = we * 64 + nf * 16 + ((grp >> 1) << 3) + li;
                int u = u0 + (grp & 1);
                uint32_t bd = base + 32768 + e * 128 + ((u ^ (e & 7)) << 4);
                uint32_t bh4[4], bl4[4];
                ldsm4(bh4, bd);
                ldsm4(bl4, bd + 16384);
                uint32_t bh0[2] = {bh4[0], bh4[1]}, bh1[2] = {bh4[2], bh4[3]};
                uint32_t bl0[2] = {bl4[0], bl4[1]}, bl1[2] = {bl4[2], bl4[3]};
                #pragma unroll
                for (int mi = 0; mi < 2; mi++) {
                    mma16816(acc[mi][nf * 2], aH[mi], bh0);
                    mma16816(acc[mi][nf * 2], aH[mi], bl0);
                    mma16816(acc[mi][nf * 2], aL[mi], bh0);
                    mma16816(acc[mi][nf * 2 + 1], aH[mi], bh1);
                    mma16816(acc[mi][nf * 2 + 1], aH[mi], bl1);
                    mma16816(acc[mi][nf * 2 + 1], aL[mi], bh1);
                }
            }
        }
        __syncthreads();
    }

    #pragma unroll
    for (int mi = 0; mi < 2; mi++) {
        long nr = n0 + wn * 32 + mi * 16;
        #pragma unroll
        for (int ni = 0; ni < 8; ni++) {
            int eg = e0 + we * 64 + ni * 8 + tg * 2;
            float2 v0, v1;
            v0.x = acc[mi][ni][0] + rsh[eg];
            v0.y = acc[mi][ni][1] + rsh[eg + 1];
            v1.x = acc[mi][ni][2] + rsh[eg];
            v1.y = acc[mi][ni][3] + rsh[eg + 1];
            *(float2*)(out + ((long)b * NN + nr + g) * DD + eg) = v0;
            *(float2*)(out + ((long)b * NN + nr + g + 8) * DD + eg) = v1;
        }
    }
}

// ---------------------------------------------------------------------------
extern "C" void kernel_launch(void* const* d_in, const int* in_sizes, int n_in,
                              void* d_out, int out_size)
{
    const float* query = (const float*)d_in[0];
    const float* key   = (const float*)d_in[1];
    const float* value = (const float*)d_in[2];
    const void*  mask  = d_in[3];
    int wo = (n_in >= 11 && in_sizes[4] == 1) ? 5 : 4;
    const float* Wq = (const float*)d_in[wo + 0];
    const float* bq = (const float*)d_in[wo + 1];
    const float* Wk = (const float*)d_in[wo + 2];
    const float* bk = (const float*)d_in[wo + 3];
    const float* Wv = (const float*)d_in[wo + 4];
    const float* bv = (const float*)d_in[wo + 5];
    float* out = (float*)d_out;

    float *pS, *pT1, *pP, *pkv1, *pkv2;
    __half *pMth, *pMtl;
    cudaGetSymbolAddress((void**)&pS, d_S);
    cudaGetSymbolAddress((void**)&pT1, d_T1);
    cudaGetSymbolAddress((void**)&pP, d_P);
    cudaGetSymbolAddress((void**)&pMth, d_Mth);
    cudaGetSymbolAddress((void**)&pMtl, d_Mtl);
    cudaGetSymbolAddress((void**)&pkv1, d_kv1);
    cudaGetSymbolAddress((void**)&pkv2, d_kv2);

    cudaFuncSetAttribute(stage1_kernel,
                         cudaFuncAttributeMaxDynamicSharedMemorySize, 2 * S1_STG);
    cudaFuncSetAttribute(stage3_kernel,
                         cudaFuncAttributeMaxDynamicSharedMemorySize, 2 * S3_STG);

    const float inv_sqrt8 = 0.35355339059327373f;

    detect_mask_kernel<<<1, 256>>>((const unsigned int*)mask);
    convert_kernel<<<NB * NCH, 256>>>(query, key, value, mask);
    stage1_kernel<<<dim3(2, 2, NB * NSPLIT), 256, 2 * S1_STG>>>();
    s_reduce_kernel<<<NB * DD * DD / 256, 256>>>();
    uvw_reduce_kernel<<<NB, DD>>>();
    kv_kernel<<<NB, DD>>>(Wk, Wv, bv);
    // T1 = Wk @ S
    sgemm_k<false, false, false, false><<<dim3(8, 4, NB), 128>>>(
        Wk, 0, pS, (long)DD * DD, pT1, nullptr, nullptr,
        nullptr, 0, nullptr, 0, nullptr, 0, nullptr, 0, 1.0f);
    // P = (T1 @ Wv^T + kv1*bv^T + bk*kv2^T) / sqrt(8)
    sgemm_k<false, true, true, false><<<dim3(8, 4, NB), 128>>>(
        pT1, (long)DD * DD, Wv, 0, pP, nullptr, nullptr,
        pkv1, DD, bv, 0, bk, 0, pkv2, DD, inv_sqrt8);
    softmax_kernel<<<dim3(NB, 4), dim3(64, 4)>>>();
    rvec_kernel<<<NB, DD>>>(bq);
    // Mt[e][d] = (aw^T @ Wq), fp16 hi/lo split epilogue
    sgemm_k<true, false, false, true><<<dim3(8, 4, NB), 128>>>(
        pP, (long)DD * DD, Wq, 0, nullptr, pMth, pMtl,
        nullptr, 0, nullptr, 0, nullptr, 0, nullptr, 0, 1.0f);
    stage3_kernel<<<dim3(64, 2, NB), 256, 2 * S3_STG>>>(out);
}

// round 8
// speedup vs baseline: 1.5388x; 1.5388x over previous
#include <cuda_runtime.h>
#include <cuda_fp16.h>
#include <math.h>
#include <stdint.h>

#define NB 8
#define NN 8192
#define DD 256
#define NSPLIT 16
#define KT 16
#define S1P 136

__device__ float d_Spart[NSPLIT * NB * DD * DD];
__device__ float d_S[NB * DD * DD];
__device__ float d_T1[NB * DD * DD];
__device__ float d_P[NB * DD * DD];
__device__ __half d_Mth[NB * DD * DD];
__device__ __half d_Mtl[NB * DD * DD];
__device__ float d_Upart[NSPLIT * NB * DD];
__device__ float d_Wpart[NSPLIT * NB * DD];
__device__ float d_Cpart[NSPLIT * NB];
__device__ float d_kv1[NB * DD];
__device__ float d_kv2[NB * DD];
__device__ float d_r[NB * DD];
__device__ int   g_mask_mode;

// ---------------- helpers ----------------
__global__ void detect_mask_kernel(const unsigned int* __restrict__ mw) {
    __shared__ int hasByte;
    if (threadIdx.x == 0) hasByte = 0;
    __syncthreads();
    int local = 0;
    for (int i = threadIdx.x; i < 16384; i += blockDim.x) {
        unsigned v = mw[i];
        if (v > 1u && v != 0x3F800000u) local = 1;
    }
    if (local) atomicOr(&hasByte, 1);
    __syncthreads();
    if (threadIdx.x == 0) g_mask_mode = hasByte ? 1 : 0;
}
__device__ __forceinline__ int mask_raw(const void* m, long i, int mode) {
    return (mode == 0) ? (((const unsigned int*)m)[i] != 0u)
                       : (((const unsigned char*)m)[i] != 0);
}
__device__ __forceinline__ void cpa16(void* s, const void* g) {
    unsigned sa = (unsigned)__cvta_generic_to_shared(s);
    asm volatile("cp.async.cg.shared.global [%0], [%1], 16;" :: "r"(sa), "l"(g));
}
#define CPA_COMMIT() asm volatile("cp.async.commit_group;" ::: "memory")
#define CPA_WAIT(n)  asm volatile("cp.async.wait_group %0;" :: "n"(n) : "memory")

__device__ __forceinline__ void mma16816(float* c, const uint32_t* a, const uint32_t* b) {
    asm volatile("mma.sync.aligned.m16n8k16.row.col.f32.f16.f16.f32 "
        "{%0,%1,%2,%3}, {%4,%5,%6,%7}, {%8,%9}, {%0,%1,%2,%3};"
        : "+f"(c[0]), "+f"(c[1]), "+f"(c[2]), "+f"(c[3])
        : "r"(a[0]), "r"(a[1]), "r"(a[2]), "r"(a[3]), "r"(b[0]), "r"(b[1]));
}
__device__ __forceinline__ void split2(float x0, float x1, uint32_t& h, uint32_t& l) {
    __half2 hh = __floats2half2_rn(x0, x1);
    __half2 ll = __floats2half2_rn(x0 - __low2float(hh), x1 - __high2float(hh));
    h = *(uint32_t*)&hh;
    l = *(uint32_t*)&ll;
}

// ---------------- stage 1: S = key_masked^T @ value (fp16x3 mma) ----------
// CTA 128d x 128e, n-chunk 512. smem [pair][row] stride 136, STS.128 stores,
// conflict-free fragment LDS. Diag blocks produce masked colsums u/w, count c.
__global__ __launch_bounds__(256, 2) void stage1_kernel(
    const float* __restrict__ key, const float* __restrict__ value,
    const void* __restrict__ mask)
{
    __shared__ uint32_t Ah[2][8 * S1P], Al[2][8 * S1P];
    __shared__ uint32_t Bh[2][8 * S1P], Bl[2][8 * S1P];
    __shared__ float cntsh[KT];

    int t = threadIdx.x, lane = t & 31, wid = t >> 5;
    int b = blockIdx.z >> 4, sp = blockIdx.z & 15;
    int d0 = blockIdx.x * 128, e0 = blockIdx.y * 128;
    int diag = (blockIdx.x == blockIdx.y);
    int zero0 = (d0 == 0 && e0 == 0);
    int mode = g_mask_mode;

    const int chunk = NN / NSPLIT;   // 512
    long nbase = (long)b * NN + (long)sp * chunk;
    const float* kb = key + nbase * DD;
    const float* vb = value + nbase * DD;

    int p = wid;                 // warp owns n-pair 2p, 2p+1 of the 16-n tile
    int dq = lane * 4;           // 4 consecutive rows (d / e index)
    int wn = wid & 3, we = wid >> 2, g = lane >> 2, tg = lane & 3;

    float acc[2][8][4];
    #pragma unroll
    for (int mi = 0; mi < 2; mi++)
        #pragma unroll
        for (int ni = 0; ni < 8; ni++)
            #pragma unroll
            for (int j = 0; j < 4; j++) acc[mi][ni][j] = 0.f;
    float colsum = 0.f, cnt = 0.f;

    float4 k0, k1, v0, v1;
    float m0, m1;
    auto ldt = [&](int kt0) {
        long n0 = nbase + kt0 + 2 * p;
        m0 = mask_raw(mask, n0, mode) ? 0.f : 1.f;
        m1 = mask_raw(mask, n0 + 1, mode) ? 0.f : 1.f;
        k0 = *(const float4*)(kb + (long)(kt0 + 2 * p) * DD + d0 + dq);
        k1 = *(const float4*)(kb + (long)(kt0 + 2 * p + 1) * DD + d0 + dq);
        v0 = *(const float4*)(vb + (long)(kt0 + 2 * p) * DD + e0 + dq);
        v1 = *(const float4*)(vb + (long)(kt0 + 2 * p + 1) * DD + e0 + dq);
    };

    const int ntiles = chunk / KT;   // 32
    ldt(0);

    for (int i = 0; i < ntiles; i++) {
        int s = i & 1;
        {   // split + vectorized transposed store
            float ka[4] = {k0.x * m0, k0.y * m0, k0.z * m0, k0.w * m0};
            float kc[4] = {k1.x * m1, k1.y * m1, k1.z * m1, k1.w * m1};
            float va[4] = {v0.x, v0.y, v0.z, v0.w};
            float vc[4] = {v1.x, v1.y, v1.z, v1.w};
            uint4 ha, la, hb, lb;
            split2(ka[0], kc[0], ha.x, la.x); split2(ka[1], kc[1], ha.y, la.y);
            split2(ka[2], kc[2], ha.z, la.z); split2(ka[3], kc[3], ha.w, la.w);
            split2(va[0], vc[0], hb.x, lb.x); split2(va[1], vc[1], hb.y, lb.y);
            split2(va[2], vc[2], hb.z, lb.z); split2(va[3], vc[3], hb.w, lb.w);
            int o = p * S1P + dq;
            *(uint4*)&Ah[s][o] = ha; *(uint4*)&Al[s][o] = la;
            *(uint4*)&Bh[s][o] = hb; *(uint4*)&Bl[s][o] = lb;
        }
        __syncthreads();
        if (i + 1 < ntiles) ldt((i + 1) * KT);

        uint32_t ah[2][4], al[2][4];
        #pragma unroll
        for (int mi = 0; mi < 2; mi++) {
            int r = wn * 32 + mi * 16 + g;
            ah[mi][0] = Ah[s][tg * S1P + r];       ah[mi][1] = Ah[s][tg * S1P + r + 8];
            ah[mi][2] = Ah[s][(tg + 4) * S1P + r]; ah[mi][3] = Ah[s][(tg + 4) * S1P + r + 8];
            al[mi][0] = Al[s][tg * S1P + r];       al[mi][1] = Al[s][tg * S1P + r + 8];
            al[mi][2] = Al[s][(tg + 4) * S1P + r]; al[mi][3] = Al[s][(tg + 4) * S1P + r + 8];
        }
        #pragma unroll
        for (int ni = 0; ni < 8; ni++) {
            int e = we * 64 + ni * 8 + g;
            uint32_t bhf[2] = {Bh[s][tg * S1P + e], Bh[s][(tg + 4) * S1P + e]};
            uint32_t blf[2] = {Bl[s][tg * S1P + e], Bl[s][(tg + 4) * S1P + e]};
            #pragma unroll
            for (int mi = 0; mi < 2; mi++) {
                mma16816(acc[mi][ni], ah[mi], bhf);
                mma16816(acc[mi][ni], ah[mi], blf);
                mma16816(acc[mi][ni], al[mi], bhf);
            }
        }
        if (diag) {
            int cc = t & 127;
            const uint32_t* Ph = (t < 128) ? &Ah[s][0] : &Bh[s][0];
            const uint32_t* Pl = (t < 128) ? &Al[s][0] : &Bl[s][0];
            float sa = 0.f;
            #pragma unroll
            for (int pp = 0; pp < 8; pp++) {
                __half2 hh = *(const __half2*)&Ph[pp * S1P + cc];
                __half2 ll = *(const __half2*)&Pl[pp * S1P + cc];
                sa += __low2float(hh) + __high2float(hh)
                    + __low2float(ll) + __high2float(ll);
            }
            colsum += sa;
        }
        if (zero0 && t < KT)
            cnt += mask_raw(mask, nbase + (long)i * KT + t, mode) ? 0.f : 1.f;
    }

    float* outp = d_Spart + ((long)(sp * NB + b) << 16);
    #pragma unroll
    for (int mi = 0; mi < 2; mi++) {
        int d = d0 + wn * 32 + mi * 16 + g;
        #pragma unroll
        for (int ni = 0; ni < 8; ni++) {
            int e = e0 + we * 64 + ni * 8 + 2 * tg;
            float2 v;
            v.x = acc[mi][ni][0]; v.y = acc[mi][ni][1];
            *(float2*)&outp[(long)d * DD + e] = v;
            v.x = acc[mi][ni][2]; v.y = acc[mi][ni][3];
            *(float2*)&outp[(long)(d + 8) * DD + e] = v;
        }
    }
    if (diag) {
        int cc = t & 127;
        if (t < 128) d_Upart[(sp * NB + b) * DD + d0 + cc] = colsum;
        else         d_Wpart[(sp * NB + b) * DD + e0 + cc] = colsum;
    }
    if (zero0) {
        if (t < KT) cntsh[t] = cnt;
        __syncthreads();
        if (t == 0) {
            float s = 0.f;
            #pragma unroll
            for (int k = 0; k < KT; k++) s += cntsh[k];
            d_Cpart[sp * NB + b] = s;
        }
    }
}

__global__ void s_reduce_kernel() {
    long i = (long)blockIdx.x * 256 + threadIdx.x;
    int b = (int)(i >> 16);
    int j = (int)(i & 65535);
    float s = 0.f;
    #pragma unroll
    for (int sp = 0; sp < NSPLIT; sp++)
        s += d_Spart[((long)(sp * NB + b) << 16) + j];
    d_S[((long)b << 16) + j] = s;
}

// fused: reduce u/w/c partials then kv1 = Wk u, kv2 = Wv w + c bv
__global__ void uvwkv_kernel(const float* __restrict__ Wk,
                             const float* __restrict__ Wv,
                             const float* __restrict__ bv) {
    __shared__ float su[DD], sw[DD], sc;
    int b = blockIdx.x, d = threadIdx.x;
    float a1 = 0.f, a2 = 0.f;
    #pragma unroll
    for (int sp = 0; sp < NSPLIT; sp++) {
        a1 += d_Upart[(sp * NB + b) * DD + d];
        a2 += d_Wpart[(sp * NB + b) * DD + d];
    }
    su[d] = a1; sw[d] = a2;
    if (d == 0) {
        float c = 0.f;
        #pragma unroll
        for (int sp = 0; sp < NSPLIT; sp++) c += d_Cpart[sp * NB + b];
        sc = c;
    }
    __syncthreads();
    float s1 = 0.f, s2 = 0.f;
    for (int i = 0; i < DD; i++) {
        s1 = fmaf(Wk[(long)d * DD + i], su[i], s1);
        s2 = fmaf(Wv[(long)d * DD + i], sw[i], s2);
    }
    d_kv1[b * DD + d] = s1;
    d_kv2[b * DD + d] = s2 + sc * bv[d];
}

// ---------------- small batched GEMM ----------------
template<bool TA, bool TB, bool EPI, bool SPL>
__global__ __launch_bounds__(128) void sgemm_k(
    const float* __restrict__ A, long sA,
    const float* __restrict__ B, long sB,
    float* __restrict__ C, __half* __restrict__ Ch, __half* __restrict__ Cl,
    const float* __restrict__ x1, int sx1,
    const float* __restrict__ y1, int sy1,
    const float* __restrict__ x2, int sx2,
    const float* __restrict__ y2, int sy2,
    float scale)
{
    __shared__ float As[16][36];
    __shared__ float Bs[16][68];
    int t = threadIdx.x;
    int b = blockIdx.z;
    int d0 = blockIdx.x * 32, e0 = blockIdx.y * 64;
    const float* Ab = A + (long)b * sA;
    const float* Bb = B + (long)b * sB;
    int td = t & 7, te = t >> 3;

    float acc[4][4];
    #pragma unroll
    for (int r = 0; r < 4; r++)
        #pragma unroll
        for (int c = 0; c < 4; c++) acc[r][c] = 0.f;

    for (int kt = 0; kt < DD; kt += 16) {
        if (TA) {
            int row = t >> 3, col = (t & 7) * 4;
            *(float4*)&As[row][col] = *(const float4*)&Ab[(long)(kt + row) * DD + d0 + col];
        } else {
            int row = t >> 2, col = (t & 3) * 4;
            float4 v = *(const float4*)&Ab[(long)(d0 + row) * DD + kt + col];
            As[col + 0][row] = v.x; As[col + 1][row] = v.y;
            As[col + 2][row] = v.z; As[col + 3][row] = v.w;
        }
        #pragma unroll
        for (int h = 0; h < 2; h++) {
            int idx = t * 4 + h * 512;
            if (TB) {
                int row = idx >> 4, col = idx & 15;
                float4 v = *(const float4*)&Bb[(long)(e0 + row) * DD + kt + col];
                Bs[col + 0][row] = v.x; Bs[col + 1][row] = v.y;
                Bs[col + 2][row] = v.z; Bs[col + 3][row] = v.w;
            } else {
                int row = idx >> 6, col = idx & 63;
                *(float4*)&Bs[row][col] = *(const float4*)&Bb[(long)(kt + row) * DD + e0 + col];
            }
        }
        __syncthreads();
        #pragma unroll
        for (int k = 0; k < 16; k++) {
            float4 a = *(const float4*)&As[k][td * 4];
            float4 bb = *(const float4*)&Bs[k][te * 4];
            float av[4] = {a.x, a.y, a.z, a.w};
            float bv2[4] = {bb.x, bb.y, bb.z, bb.w};
            #pragma unroll
            for (int r = 0; r < 4; r++)
                #pragma unroll
                for (int c = 0; c < 4; c++)
                    acc[r][c] = fmaf(av[r], bv2[c], acc[r][c]);
        }
        __syncthreads();
    }

    #pragma unroll
    for (int r = 0; r < 4; r++) {
        int d = d0 + td * 4 + r;
        #pragma unroll
        for (int c = 0; c < 4; c++) {
            int e = e0 + te * 4 + c;
            float v = acc[r][c];
            if (EPI)
                v = (v + x1[b * sx1 + d] * y1[b * sy1 + e]
                       + x2[b * sx2 + d] * y2[b * sy2 + e]) * scale;
            long offo = ((long)b << 16) + (long)d * DD + e;
            if (SPL) {
                __half h = __float2half_rn(v);
                Ch[offo] = h;
                Cl[offo] = __float2half_rn(v - __half2float(h));
            } else {
                C[offo] = v;
            }
        }
    }
}

// ---------------- softmax over d (in-place d_P) + fused r = bq^T aw --------
__global__ void softmax_kernel(const float* __restrict__ bq) {
    int b = blockIdx.x, ec = blockIdx.y;
    int tx = threadIdx.x, ty = threadIdx.y;
    float* Pb = d_P + ((long)b << 16);
    int e = ec * 64 + tx;
    __shared__ float red[4][64];

    float mx = -3.4e38f;
    for (int d = ty; d < DD; d += 4) mx = fmaxf(mx, Pb[(long)d * DD + e]);
    red[ty][tx] = mx;
    __syncthreads();
    mx = fmaxf(fmaxf(red[0][tx], red[1][tx]), fmaxf(red[2][tx], red[3][tx]));
    __syncthreads();
    float s = 0.f;
    for (int d = ty; d < DD; d += 4) {
        float ev = expf(Pb[(long)d * DD + e] - mx);
        Pb[(long)d * DD + e] = ev;
        s += ev;
    }
    red[ty][tx] = s;
    __syncthreads();
    float inv = 1.0f / (red[0][tx] + red[1][tx] + red[2][tx] + red[3][tx]);
    __syncthreads();
    float rr = 0.f;
    for (int d = ty; d < DD; d += 4) {
        float val = Pb[(long)d * DD + e] * inv;
        Pb[(long)d * DD + e] = val;
        rr = fmaf(bq[d], val, rr);
    }
    red[ty][tx] = rr;
    __syncthreads();
    if (ty == 0)
        d_r[b * DD + e] = red[0][tx] + red[1][tx] + red[2][tx] + red[3][tx];
}

// ---------------- stage 3: out = q @ M + r (fp16x3 mma) --------------------
// CTA 128n x 128e, K=256 in chunks of 32, double buffered, 2 CTAs/SM.
#define S3_SMEM (2 * 2560 * 16)
__device__ __forceinline__ int offA32(int r, int kp) {
    return (r * 5 + ((kp >> 2) ^ (r & 3))) * 4 + (kp & 3);
}

__global__ __launch_bounds__(256, 2) void stage3_kernel(
    const float* __restrict__ query, float* __restrict__ out)
{
    extern __shared__ uint4 sm[];
    __shared__ float rsh[DD];
    int t = threadIdx.x, lane = t & 31, wid = t >> 5;
    int b = blockIdx.z;
    long n0 = (long)blockIdx.x * 128;
    int e0 = blockIdx.y * 128;
    const float* qb = query + ((long)b * NN + n0) * DD;
    const __half* Bhp = d_Mth + ((long)b << 16) + (long)e0 * DD;
    const __half* Blp = d_Mtl + ((long)b << 16) + (long)e0 * DD;
    if (t < DD) rsh[t] = d_r[b * DD + t];

    int wn = wid & 3, we = wid >> 2, g = lane >> 2, tg = lane & 3;

    auto issueB = [&](int c, int s) {
        uint4* BH = sm + s * 2560 + 1280;
        uint4* BL = BH + 640;
        #pragma unroll
        for (int a = 0; a < 2; a++) {
            int idx = t + a * 256, e = idx >> 2, u = idx & 3;
            int i16 = e * 5 + (u ^ (e & 3));
            cpa16(&BH[i16], Bhp + (long)e * DD + c * 32 + u * 8);
            cpa16(&BL[i16], Blp + (long)e * DD + c * 32 + u * 8);
        }
        CPA_COMMIT();
    };
    auto loadA = [&](int c, int s) {
        uint4* AH = sm + s * 2560;
        uint4* AL = AH + 640;
        #pragma unroll
        for (int a = 0; a < 2; a++) {
            int idx = t + a * 256, row = idx >> 2, u = idx & 3;
            const float* src = qb + (long)row * DD + c * 32 + u * 8;
            float4 f0 = *(const float4*)src;
            float4 f1 = *(const float4*)(src + 4);
            uint32_t h0, l0, h1, l1, h2, l2, h3, l3;
            split2(f0.x, f0.y, h0, l0); split2(f0.z, f0.w, h1, l1);
            split2(f1.x, f1.y, h2, l2); split2(f1.z, f1.w, h3, l3);
            int i16 = row * 5 + (u ^ (row & 3));
            AH[i16] = make_uint4(h0, h1, h2, h3);
            AL[i16] = make_uint4(l0, l1, l2, l3);
        }
    };

    float acc[2][8][4];
    #pragma unroll
    for (int mi = 0; mi < 2; mi++)
        #pragma unroll
        for (int ni = 0; ni < 8; ni++)
            #pragma unroll
            for (int j = 0; j < 4; j++) acc[mi][ni][j] = 0.f;

    issueB(0, 0);

    for (int c = 0; c < 8; c++) {
        int s = c & 1;
        loadA(c, s);
        if (c < 7) { issueB(c + 1, 1 - s); CPA_WAIT(1); }
        else       { CPA_WAIT(0); }
        __syncthreads();

        const uint32_t* AH = (const uint32_t*)(sm + s * 2560);
        const uint32_t* AL = AH + 2560;
        const uint32_t* BH = AH + 5120;
        const uint32_t* BL = AH + 7680;
        #pragma unroll
        for (int j = 0; j < 2; j++) {
            int kp0 = j * 8 + tg, kp1 = kp0 + 4;
            uint32_t ah[2][4], al[2][4];
            #pragma unroll
            for (int mi = 0; mi < 2; mi++) {
                int r = wn * 32 + mi * 16 + g;
                ah[mi][0] = AH[offA32(r, kp0)];     ah[mi][1] = AH[offA32(r + 8, kp0)];
                ah[mi][2] = AH[offA32(r, kp1)];     ah[mi][3] = AH[offA32(r + 8, kp1)];
                al[mi][0] = AL[offA32(r, kp0)];     al[mi][1] = AL[offA32(r + 8, kp0)];
                al[mi][2] = AL[offA32(r, kp1)];     al[mi][3] = AL[offA32(r + 8, kp1)];
            }
            #pragma unroll
            for (int ni = 0; ni < 8; ni++) {
                int e = we * 64 + ni * 8 + g;
                uint32_t bhf[2] = {BH[offA32(e, kp0)], BH[offA32(e, kp1)]};
                uint32_t blf[2] = {BL[offA32(e, kp0)], BL[offA32(e, kp1)]};
                #pragma unroll
                for (int mi = 0; mi < 2; mi++) {
                    mma16816(acc[mi][ni], ah[mi], bhf);
                    mma16816(acc[mi][ni], ah[mi], blf);
                    mma16816(acc[mi][ni], al[mi], bhf);
                }
            }
        }
        __syncthreads();
    }

    #pragma unroll
    for (int mi = 0; mi < 2; mi++) {
        long nr = n0 + wn * 32 + mi * 16;
        #pragma unroll
        for (int ni = 0; ni < 8; ni++) {
            int eg = e0 + we * 64 + ni * 8 + tg * 2;
            float2 v0, v1;
            v0.x = acc[mi][ni][0] + rsh[eg];
            v0.y = acc[mi][ni][1] + rsh[eg + 1];
            v1.x = acc[mi][ni][2] + rsh[eg];
            v1.y = acc[mi][ni][3] + rsh[eg + 1];
            *(float2*)(out + ((long)b * NN + nr + g) * DD + eg) = v0;
            *(float2*)(out + ((long)b * NN + nr + g + 8) * DD + eg) = v1;
        }
    }
}

// ---------------------------------------------------------------------------
extern "C" void kernel_launch(void* const* d_in, const int* in_sizes, int n_in,
                              void* d_out, int out_size)
{
    const float* query = (const float*)d_in[0];
    const float* key   = (const float*)d_in[1];
    const float* value = (const float*)d_in[2];
    const void*  mask  = d_in[3];
    int wo = (n_in >= 11 && in_sizes[4] == 1) ? 5 : 4;
    const float* Wq = (const float*)d_in[wo + 0];
    const float* bq = (const float*)d_in[wo + 1];
    const float* Wk = (const float*)d_in[wo + 2];
    const float* bk = (const float*)d_in[wo + 3];
    const float* Wv = (const float*)d_in[wo + 4];
    const float* bv = (const float*)d_in[wo + 5];
    float* out = (float*)d_out;

    float *pS, *pT1, *pP, *pkv1, *pkv2;
    __half *pMth, *pMtl;
    cudaGetSymbolAddress((void**)&pS, d_S);
    cudaGetSymbolAddress((void**)&pT1, d_T1);
    cudaGetSymbolAddress((void**)&pP, d_P);
    cudaGetSymbolAddress((void**)&pMth, d_Mth);
    cudaGetSymbolAddress((void**)&pMtl, d_Mtl);
    cudaGetSymbolAddress((void**)&pkv1, d_kv1);
    cudaGetSymbolAddress((void**)&pkv2, d_kv2);

    cudaFuncSetAttribute(stage3_kernel,
                         cudaFuncAttributeMaxDynamicSharedMemorySize, S3_SMEM);

    const float inv_sqrt8 = 0.35355339059327373f;

    detect_mask_kernel<<<1, 256>>>((const unsigned int*)mask);
    stage1_kernel<<<dim3(2, 2, NB * NSPLIT), 256>>>(key, value, mask);
    s_reduce_kernel<<<NB * DD * DD / 256, 256>>>();
    uvwkv_kernel<<<NB, DD>>>(Wk, Wv, bv);
    // T1 = Wk @ S
    sgemm_k<false, false, false, false><<<dim3(8, 4, NB), 128>>>(
        Wk, 0, pS, (long)DD * DD, pT1, nullptr, nullptr,
        nullptr, 0, nullptr, 0, nullptr, 0, nullptr, 0, 1.0f);
    // P = (T1 @ Wv^T + kv1*bv^T + bk*kv2^T) / sqrt(8)
    sgemm_k<false, true, true, false><<<dim3(8, 4, NB), 128>>>(
        pT1, (long)DD * DD, Wv, 0, pP, nullptr, nullptr,
        pkv1, DD, bv, 0, bk, 0, pkv2, DD, inv_sqrt8);
    softmax_kernel<<<dim3(NB, 4), dim3(64, 4)>>>(bq);
    // Mt[e][d] = (aw^T @ Wq), fp16 hi/lo split epilogue
    sgemm_k<true, false, false, true><<<dim3(8, 4, NB), 128>>>(
        pP, (long)DD * DD, Wq, 0, nullptr, pMth, pMtl,
        nullptr, 0, nullptr, 0, nullptr, 0, nullptr, 0, 1.0f);
    stage3_kernel<<<dim3(64, 2, NB), 256, S3_SMEM>>>(query, out);
}

// round 9
// speedup vs baseline: 1.9029x; 1.2367x over previous
#include <cuda_runtime.h>
#include <cuda_fp16.h>
#include <math.h>
#include <stdint.h>

#define NB 8
#define NN 8192
#define DD 256
#define NSPLIT 16
#define KT 16
#define S1P 136

__device__ float d_Spart[NSPLIT * NB * DD * DD];
__device__ float d_S[NB * DD * DD];
__device__ float d_T1[NB * DD * DD];
__device__ float d_P[NB * DD * DD];
__device__ __half d_Mth[NB * DD * DD];
__device__ __half d_Mtl[NB * DD * DD];
__device__ float d_Upart[NSPLIT * NB * DD];
__device__ float d_Wpart[NSPLIT * NB * DD];
__device__ float d_Cpart[NSPLIT * NB];
__device__ float d_kv1[NB * DD];
__device__ float d_kv2[NB * DD];
__device__ float d_r[NB * DD];
__device__ int   g_mask_mode;

// ---------------- helpers ----------------
__global__ void detect_mask_kernel(const unsigned int* __restrict__ mw) {
    __shared__ int hasByte;
    if (threadIdx.x == 0) hasByte = 0;
    __syncthreads();
    int local = 0;
    for (int i = threadIdx.x; i < 16384; i += blockDim.x) {
        unsigned v = mw[i];
        if (v > 1u && v != 0x3F800000u) local = 1;
    }
    if (local) atomicOr(&hasByte, 1);
    __syncthreads();
    if (threadIdx.x == 0) g_mask_mode = hasByte ? 1 : 0;
}
__device__ __forceinline__ int mask_raw(const void* m, long i, int mode) {
    return (mode == 0) ? (((const unsigned int*)m)[i] != 0u)
                       : (((const unsigned char*)m)[i] != 0);
}
__device__ __forceinline__ void cpa16(void* s, const void* g) {
    unsigned sa = (unsigned)__cvta_generic_to_shared(s);
    asm volatile("cp.async.cg.shared.global [%0], [%1], 16;" :: "r"(sa), "l"(g));
}
#define CPA_COMMIT() asm volatile("cp.async.commit_group;" ::: "memory")
#define CPA_WAIT(n)  asm volatile("cp.async.wait_group %0;" :: "n"(n) : "memory")

__device__ __forceinline__ void mma16816(float* c, const uint32_t* a, const uint32_t* b) {
    asm volatile("mma.sync.aligned.m16n8k16.row.col.f32.f16.f16.f32 "
        "{%0,%1,%2,%3}, {%4,%5,%6,%7}, {%8,%9}, {%0,%1,%2,%3};"
        : "+f"(c[0]), "+f"(c[1]), "+f"(c[2]), "+f"(c[3])
        : "r"(a[0]), "r"(a[1]), "r"(a[2]), "r"(a[3]), "r"(b[0]), "r"(b[1]));
}
__device__ __forceinline__ void split2(float x0, float x1, uint32_t& h, uint32_t& l) {
    __half2 hh = __floats2half2_rn(x0, x1);
    __half2 ll = __floats2half2_rn(x0 - __low2float(hh), x1 - __high2float(hh));
    h = *(uint32_t*)&hh;
    l = *(uint32_t*)&ll;
}

// ---------------- stage 1: S = key_masked^T @ value (fp16x3 mma) ----------
__global__ __launch_bounds__(256, 2) void stage1_kernel(
    const float* __restrict__ key, const float* __restrict__ value,
    const void* __restrict__ mask)
{
    __shared__ uint32_t Ah[2][8 * S1P], Al[2][8 * S1P];
    __shared__ uint32_t Bh[2][8 * S1P], Bl[2][8 * S1P];
    __shared__ float cntsh[KT];

    int t = threadIdx.x, lane = t & 31, wid = t >> 5;
    int b = blockIdx.z >> 4, sp = blockIdx.z & 15;
    int d0 = blockIdx.x * 128, e0 = blockIdx.y * 128;
    int diag = (blockIdx.x == blockIdx.y);
    int zero0 = (d0 == 0 && e0 == 0);
    int mode = g_mask_mode;

    const int chunk = NN / NSPLIT;   // 512
    long nbase = (long)b * NN + (long)sp * chunk;
    const float* kb = key + nbase * DD;
    const float* vb = value + nbase * DD;

    int p = wid;
    int dq = lane * 4;
    int wn = wid & 3, we = wid >> 2, g = lane >> 2, tg = lane & 3;

    float acc[2][8][4];
    #pragma unroll
    for (int mi = 0; mi < 2; mi++)
        #pragma unroll
        for (int ni = 0; ni < 8; ni++)
            #pragma unroll
            for (int j = 0; j < 4; j++) acc[mi][ni][j] = 0.f;
    float colsum = 0.f, cnt = 0.f;

    float4 k0, k1, v0, v1;
    float m0, m1;
    auto ldt = [&](int kt0) {
        long n0 = nbase + kt0 + 2 * p;
        m0 = mask_raw(mask, n0, mode) ? 0.f : 1.f;
        m1 = mask_raw(mask, n0 + 1, mode) ? 0.f : 1.f;
        k0 = *(const float4*)(kb + (long)(kt0 + 2 * p) * DD + d0 + dq);
        k1 = *(const float4*)(kb + (long)(kt0 + 2 * p + 1) * DD + d0 + dq);
        v0 = *(const float4*)(vb + (long)(kt0 + 2 * p) * DD + e0 + dq);
        v1 = *(const float4*)(vb + (long)(kt0 + 2 * p + 1) * DD + e0 + dq);
    };

    const int ntiles = chunk / KT;   // 32
    ldt(0);

    for (int i = 0; i < ntiles; i++) {
        int s = i & 1;
        {
            float ka[4] = {k0.x * m0, k0.y * m0, k0.z * m0, k0.w * m0};
            float kc[4] = {k1.x * m1, k1.y * m1, k1.z * m1, k1.w * m1};
            float va[4] = {v0.x, v0.y, v0.z, v0.w};
            float vc[4] = {v1.x, v1.y, v1.z, v1.w};
            uint4 ha, la, hb, lb;
            split2(ka[0], kc[0], ha.x, la.x); split2(ka[1], kc[1], ha.y, la.y);
            split2(ka[2], kc[2], ha.z, la.z); split2(ka[3], kc[3], ha.w, la.w);
            split2(va[0], vc[0], hb.x, lb.x); split2(va[1], vc[1], hb.y, lb.y);
            split2(va[2], vc[2], hb.z, lb.z); split2(va[3], vc[3], hb.w, lb.w);
            int o = p * S1P + dq;
            *(uint4*)&Ah[s][o] = ha; *(uint4*)&Al[s][o] = la;
            *(uint4*)&Bh[s][o] = hb; *(uint4*)&Bl[s][o] = lb;
        }
        __syncthreads();
        if (i + 1 < ntiles) ldt((i + 1) * KT);

        uint32_t ah[2][4], al[2][4];
        #pragma unroll
        for (int mi = 0; mi < 2; mi++) {
            int r = wn * 32 + mi * 16 + g;
            ah[mi][0] = Ah[s][tg * S1P + r];       ah[mi][1] = Ah[s][tg * S1P + r + 8];
            ah[mi][2] = Ah[s][(tg + 4) * S1P + r]; ah[mi][3] = Ah[s][(tg + 4) * S1P + r + 8];
            al[mi][0] = Al[s][tg * S1P + r];       al[mi][1] = Al[s][tg * S1P + r + 8];
            al[mi][2] = Al[s][(tg + 4) * S1P + r]; al[mi][3] = Al[s][(tg + 4) * S1P + r + 8];
        }
        #pragma unroll
        for (int ni = 0; ni < 8; ni++) {
            int e = we * 64 + ni * 8 + g;
            uint32_t bhf[2] = {Bh[s][tg * S1P + e], Bh[s][(tg + 4) * S1P + e]};
            uint32_t blf[2] = {Bl[s][tg * S1P + e], Bl[s][(tg + 4) * S1P + e]};
            #pragma unroll
            for (int mi = 0; mi < 2; mi++) {
                mma16816(acc[mi][ni], ah[mi], bhf);
                mma16816(acc[mi][ni], ah[mi], blf);
                mma16816(acc[mi][ni], al[mi], bhf);
            }
        }
        if (diag) {
            int cc = t & 127;
            const uint32_t* Ph = (t < 128) ? &Ah[s][0] : &Bh[s][0];
            const uint32_t* Pl = (t < 128) ? &Al[s][0] : &Bl[s][0];
            float sa = 0.f;
            #pragma unroll
            for (int pp = 0; pp < 8; pp++) {
                __half2 hh = *(const __half2*)&Ph[pp * S1P + cc];
                __half2 ll = *(const __half2*)&Pl[pp * S1P + cc];
                sa += __low2float(hh) + __high2float(hh)
                    + __low2float(ll) + __high2float(ll);
            }
            colsum += sa;
        }
        if (zero0 && t < KT)
            cnt += mask_raw(mask, nbase + (long)i * KT + t, mode) ? 0.f : 1.f;
    }

    float* outp = d_Spart + ((long)(sp * NB + b) << 16);
    #pragma unroll
    for (int mi = 0; mi < 2; mi++) {
        int d = d0 + wn * 32 + mi * 16 + g;
        #pragma unroll
        for (int ni = 0; ni < 8; ni++) {
            int e = e0 + we * 64 + ni * 8 + 2 * tg;
            float2 v;
            v.x = acc[mi][ni][0]; v.y = acc[mi][ni][1];
            *(float2*)&outp[(long)d * DD + e] = v;
            v.x = acc[mi][ni][2]; v.y = acc[mi][ni][3];
            *(float2*)&outp[(long)(d + 8) * DD + e] = v;
        }
    }
    if (diag) {
        int cc = t & 127;
        if (t < 128) d_Upart[(sp * NB + b) * DD + d0 + cc] = colsum;
        else         d_Wpart[(sp * NB + b) * DD + e0 + cc] = colsum;
    }
    if (zero0) {
        if (t < KT) cntsh[t] = cnt;
        __syncthreads();
        if (t == 0) {
            float s = 0.f;
            #pragma unroll
            for (int k = 0; k < KT; k++) s += cntsh[k];
            d_Cpart[sp * NB + b] = s;
        }
    }
}

// vectorized partial reduce: 4 floats/thread
__global__ void s_reduce_kernel() {
    long i = ((long)blockIdx.x * 256 + threadIdx.x) * 4;   // element index
    int b = (int)(i >> 16);
    int j = (int)(i & 65535);
    float4 s = make_float4(0.f, 0.f, 0.f, 0.f);
    #pragma unroll
    for (int sp = 0; sp < NSPLIT; sp++) {
        float4 v = *(const float4*)&d_Spart[((long)(sp * NB + b) << 16) + j];
        s.x += v.x; s.y += v.y; s.z += v.z; s.w += v.w;
    }
    *(float4*)&d_S[((long)b << 16) + j] = s;
}

// fused uvw reduce + kv matvecs. grid (NB, 8); warp computes 4 output rows,
// 8 lanes per row striding the k-dim in float4s (coalesced), shfl reduce.
__global__ __launch_bounds__(256) void uvwkv_kernel(
    const float* __restrict__ Wk, const float* __restrict__ Wv,
    const float* __restrict__ bv)
{
    __shared__ float su[DD], sw[DD];
    __shared__ float scc;
    int b = blockIdx.x, dblk = blockIdx.y;
    int t = threadIdx.x, lane = t & 31, wid = t >> 5;

    float a1 = 0.f, a2 = 0.f;
    #pragma unroll
    for (int sp = 0; sp < NSPLIT; sp++) {
        a1 += d_Upart[(sp * NB + b) * DD + t];
        a2 += d_Wpart[(sp * NB + b) * DD + t];
    }
    su[t] = a1; sw[t] = a2;
    if (t == 0) {
        float c = 0.f;
        #pragma unroll
        for (int sp = 0; sp < NSPLIT; sp++) c += d_Cpart[sp * NB + b];
        scc = c;
    }
    __syncthreads();

    int sub = lane >> 3, li = lane & 7;          // 4 rows/warp, 8 lanes/row
    int d = dblk * 32 + wid * 4 + sub;
    const float* wk = Wk + (long)d * DD;
    const float* wv = Wv + (long)d * DD;
    float s1 = 0.f, s2 = 0.f;
    #pragma unroll
    for (int ii = 0; ii < 8; ii++) {
        int c4 = (li + ii * 8) * 4;
        float4 wa = *(const float4*)(wk + c4);
        float4 ua = *(const float4*)(su + c4);
        float4 wb = *(const float4*)(wv + c4);
        float4 va = *(const float4*)(sw + c4);
        s1 += wa.x * ua.x + wa.y * ua.y + wa.z * ua.z + wa.w * ua.w;
        s2 += wb.x * va.x + wb.y * va.y + wb.z * va.z + wb.w * va.w;
    }
    #pragma unroll
    for (int m = 4; m; m >>= 1) {
        s1 += __shfl_xor_sync(0xFFFFFFFFu, s1, m);
        s2 += __shfl_xor_sync(0xFFFFFFFFu, s2, m);
    }
    if (li == 0) {
        d_kv1[b * DD + d] = s1;
        d_kv2[b * DD + d] = s2 + scc * bv[d];
    }
}

// ---------------- small batched GEMM ----------------
template<bool TA, bool TB, bool EPI, bool SPL>
__global__ __launch_bounds__(128) void sgemm_k(
    const float* __restrict__ A, long sA,
    const float* __restrict__ B, long sB,
    float* __restrict__ C, __half* __restrict__ Ch, __half* __restrict__ Cl,
    const float* __restrict__ x1, int sx1,
    const float* __restrict__ y1, int sy1,
    const float* __restrict__ x2, int sx2,
    const float* __restrict__ y2, int sy2,
    float scale)
{
    __shared__ float As[16][36];
    __shared__ float Bs[16][68];
    int t = threadIdx.x;
    int b = blockIdx.z;
    int d0 = blockIdx.x * 32, e0 = blockIdx.y * 64;
    const float* Ab = A + (long)b * sA;
    const float* Bb = B + (long)b * sB;
    int td = t & 7, te = t >> 3;

    float acc[4][4];
    #pragma unroll
    for (int r = 0; r < 4; r++)
        #pragma unroll
        for (int c = 0; c < 4; c++) acc[r][c] = 0.f;

    for (int kt = 0; kt < DD; kt += 16) {
        if (TA) {
            int row = t >> 3, col = (t & 7) * 4;
            *(float4*)&As[row][col] = *(const float4*)&Ab[(long)(kt + row) * DD + d0 + col];
        } else {
            int row = t >> 2, col = (t & 3) * 4;
            float4 v = *(const float4*)&Ab[(long)(d0 + row) * DD + kt + col];
            As[col + 0][row] = v.x; As[col + 1][row] = v.y;
            As[col + 2][row] = v.z; As[col + 3][row] = v.w;
        }
        #pragma unroll
        for (int h = 0; h < 2; h++) {
            int idx = t * 4 + h * 512;
            if (TB) {
                int row = idx >> 4, col = idx & 15;
                float4 v = *(const float4*)&Bb[(long)(e0 + row) * DD + kt + col];
                Bs[col + 0][row] = v.x; Bs[col + 1][row] = v.y;
                Bs[col + 2][row] = v.z; Bs[col + 3][row] = v.w;
            } else {
                int row = idx >> 6, col = idx & 63;
                *(float4*)&Bs[row][col] = *(const float4*)&Bb[(long)(kt + row) * DD + e0 + col];
            }
        }
        __syncthreads();
        #pragma unroll
        for (int k = 0; k < 16; k++) {
            float4 a = *(const float4*)&As[k][td * 4];
            float4 bb = *(const float4*)&Bs[k][te * 4];
            float av[4] = {a.x, a.y, a.z, a.w};
            float bv2[4] = {bb.x, bb.y, bb.z, bb.w};
            #pragma unroll
            for (int r = 0; r < 4; r++)
                #pragma unroll
                for (int c = 0; c < 4; c++)
                    acc[r][c] = fmaf(av[r], bv2[c], acc[r][c]);
        }
        __syncthreads();
    }

    #pragma unroll
    for (int r = 0; r < 4; r++) {
        int d = d0 + td * 4 + r;
        #pragma unroll
        for (int c = 0; c < 4; c++) {
            int e = e0 + te * 4 + c;
            float v = acc[r][c];
            if (EPI)
                v = (v + x1[b * sx1 + d] * y1[b * sy1 + e]
                       + x2[b * sx2 + d] * y2[b * sy2 + e]) * scale;
            long offo = ((long)b << 16) + (long)d * DD + e;
            if (SPL) {
                __half h = __float2half_rn(v);
                Ch[offo] = h;
                Cl[offo] = __float2half_rn(v - __half2float(h));
            } else {
                C[offo] = v;
            }
        }
    }
}

// ---------------- softmax + fused r = bq^T aw ----------------
__global__ void softmax_kernel(const float* __restrict__ bq) {
    int b = blockIdx.x, ec = blockIdx.y;
    int tx = threadIdx.x, ty = threadIdx.y;
    float* Pb = d_P + ((long)b << 16);
    int e = ec * 64 + tx;
    __shared__ float red[4][64];

    float mx = -3.4e38f;
    for (int d = ty; d < DD; d += 4) mx = fmaxf(mx, Pb[(long)d * DD + e]);
    red[ty][tx] = mx;
    __syncthreads();
    mx = fmaxf(fmaxf(red[0][tx], red[1][tx]), fmaxf(red[2][tx], red[3][tx]));
    __syncthreads();
    float s = 0.f;
    for (int d = ty; d < DD; d += 4) {
        float ev = expf(Pb[(long)d * DD + e] - mx);
        Pb[(long)d * DD + e] = ev;
        s += ev;
    }
    red[ty][tx] = s;
    __syncthreads();
    float inv = 1.0f / (red[0][tx] + red[1][tx] + red[2][tx] + red[3][tx]);
    __syncthreads();
    float rr = 0.f;
    for (int d = ty; d < DD; d += 4) {
        float val = Pb[(long)d * DD + e] * inv;
        Pb[(long)d * DD + e] = val;
        rr = fmaf(bq[d], val, rr);
    }
    red[ty][tx] = rr;
    __syncthreads();
    if (ty == 0)
        d_r[b * DD + e] = red[0][tx] + red[1][tx] + red[2][tx] + red[3][tx];
}

// ---------------- stage 3: out = q @ M + r (fp16x3 mma) --------------------
#define S3_SMEM (2 * 2560 * 16)
__device__ __forceinline__ int offA32(int r, int kp) {
    return (r * 5 + ((kp >> 2) ^ (r & 3))) * 4 + (kp & 3);
}

__global__ __launch_bounds__(256, 2) void stage3_kernel(
    const float* __restrict__ query, float* __restrict__ out)
{
    extern __shared__ uint4 sm[];
    __shared__ float rsh[DD];
    int t = threadIdx.x, lane = t & 31, wid = t >> 5;
    int b = blockIdx.z;
    long n0 = (long)blockIdx.x * 128;
    int e0 = blockIdx.y * 128;
    const float* qb = query + ((long)b * NN + n0) * DD;
    const __half* Bhp = d_Mth + ((long)b << 16) + (long)e0 * DD;
    const __half* Blp = d_Mtl + ((long)b << 16) + (long)e0 * DD;
    if (t < DD) rsh[t] = d_r[b * DD + t];

    int wn = wid & 3, we = wid >> 2, g = lane >> 2, tg = lane & 3;

    auto issueB = [&](int c, int s) {
        uint4* BH = sm + s * 2560 + 1280;
        uint4* BL = BH + 640;
        #pragma unroll
        for (int a = 0; a < 2; a++) {
            int idx = t + a * 256, e = idx >> 2, u = idx & 3;
            int i16 = e * 5 + (u ^ (e & 3));
            cpa16(&BH[i16], Bhp + (long)e * DD + c * 32 + u * 8);
            cpa16(&BL[i16], Blp + (long)e * DD + c * 32 + u * 8);
        }
        CPA_COMMIT();
    };
    auto loadA = [&](int c, int s) {
        uint4* AH = sm + s * 2560;
        uint4* AL = AH + 640;
        #pragma unroll
        for (int a = 0; a < 2; a++) {
            int idx = t + a * 256, row = idx >> 2, u = idx & 3;
            const float* src = qb + (long)row * DD + c * 32 + u * 8;
            float4 f0 = *(const float4*)src;
            float4 f1 = *(const float4*)(src + 4);
            uint32_t h0, l0, h1, l1, h2, l2, h3, l3;
            split2(f0.x, f0.y, h0, l0); split2(f0.z, f0.w, h1, l1);
            split2(f1.x, f1.y, h2, l2); split2(f1.z, f1.w, h3, l3);
            int i16 = row * 5 + (u ^ (row & 3));
            AH[i16] = make_uint4(h0, h1, h2, h3);
            AL[i16] = make_uint4(l0, l1, l2, l3);
        }
    };

    float acc[2][8][4];
    #pragma unroll
    for (int mi = 0; mi < 2; mi++)
        #pragma unroll
        for (int ni = 0; ni < 8; ni++)
            #pragma unroll
            for (int j = 0; j < 4; j++) acc[mi][ni][j] = 0.f;

    issueB(0, 0);

    for (int c = 0; c < 8; c++) {
        int s = c & 1;
        loadA(c, s);
        if (c < 7) { issueB(c + 1, 1 - s); CPA_WAIT(1); }
        else       { CPA_WAIT(0); }
        __syncthreads();

        const uint32_t* AH = (const uint32_t*)(sm + s * 2560);
        const uint32_t* AL = AH + 2560;
        const uint32_t* BH = AH + 5120;
        const uint32_t* BL = AH + 7680;
        #pragma unroll
        for (int j = 0; j < 2; j++) {
            int kp0 = j * 8 + tg, kp1 = kp0 + 4;
            uint32_t ah[2][4], al[2][4];
            #pragma unroll
            for (int mi = 0; mi < 2; mi++) {
                int r = wn * 32 + mi * 16 + g;
                ah[mi][0] = AH[offA32(r, kp0)];     ah[mi][1] = AH[offA32(r + 8, kp0)];
                ah[mi][2] = AH[offA32(r, kp1)];     ah[mi][3] = AH[offA32(r + 8, kp1)];
                al[mi][0] = AL[offA32(r, kp0)];     al[mi][1] = AL[offA32(r + 8, kp0)];
                al[mi][2] = AL[offA32(r, kp1)];     al[mi][3] = AL[offA32(r + 8, kp1)];
            }
            #pragma unroll
            for (int ni = 0; ni < 8; ni++) {
                int e = we * 64 + ni * 8 + g;
                uint32_t bhf[2] = {BH[offA32(e, kp0)], BH[offA32(e, kp1)]};
                uint32_t blf[2] = {BL[offA32(e, kp0)], BL[offA32(e, kp1)]};
                #pragma unroll
                for (int mi = 0; mi < 2; mi++) {
                    mma16816(acc[mi][ni], ah[mi], bhf);
                    mma16816(acc[mi][ni], ah[mi], blf);
                    mma16816(acc[mi][ni], al[mi], bhf);
                }
            }
        }
        __syncthreads();
    }

    #pragma unroll
    for (int mi = 0; mi < 2; mi++) {
        long nr = n0 + wn * 32 + mi * 16;
        #pragma unroll
        for (int ni = 0; ni < 8; ni++) {
            int eg = e0 + we * 64 + ni * 8 + tg * 2;
            float2 v0, v1;
            v0.x = acc[mi][ni][0] + rsh[eg];
            v0.y = acc[mi][ni][1] + rsh[eg + 1];
            v1.x = acc[mi][ni][2] + rsh[eg];
            v1.y = acc[mi][ni][3] + rsh[eg + 1];
            *(float2*)(out + ((long)b * NN + nr + g) * DD + eg) = v0;
            *(float2*)(out + ((long)b * NN + nr + g + 8) * DD + eg) = v1;
        }
    }
}

// ---------------------------------------------------------------------------
extern "C" void kernel_launch(void* const* d_in, const int* in_sizes, int n_in,
                              void* d_out, int out_size)
{
    const float* query = (const float*)d_in[0];
    const float* key   = (const float*)d_in[1];
    const float* value = (const float*)d_in[2];
    const void*  mask  = d_in[3];
    int wo = (n_in >= 11 && in_sizes[4] == 1) ? 5 : 4;
    const float* Wq = (const float*)d_in[wo + 0];
    const float* bq = (const float*)d_in[wo + 1];
    const float* Wk = (const float*)d_in[wo + 2];
    const float* bk = (const float*)d_in[wo + 3];
    const float* Wv = (const float*)d_in[wo + 4];
    const float* bv = (const float*)d_in[wo + 5];
    float* out = (float*)d_out;

    float *pS, *pT1, *pP, *pkv1, *pkv2;
    __half *pMth, *pMtl;
    cudaGetSymbolAddress((void**)&pS, d_S);
    cudaGetSymbolAddress((void**)&pT1, d_T1);
    cudaGetSymbolAddress((void**)&pP, d_P);
    cudaGetSymbolAddress((void**)&pMth, d_Mth);
    cudaGetSymbolAddress((void**)&pMtl, d_Mtl);
    cudaGetSymbolAddress((void**)&pkv1, d_kv1);
    cudaGetSymbolAddress((void**)&pkv2, d_kv2);

    cudaFuncSetAttribute(stage3_kernel,
                         cudaFuncAttributeMaxDynamicSharedMemorySize, S3_SMEM);

    const float inv_sqrt8 = 0.35355339059327373f;

    detect_mask_kernel<<<1, 256>>>((const unsigned int*)mask);
    stage1_kernel<<<dim3(2, 2, NB * NSPLIT), 256>>>(key, value, mask);
    s_reduce_kernel<<<NB * DD * DD / 1024, 256>>>();
    uvwkv_kernel<<<dim3(NB, 8), 256>>>(Wk, Wv, bv);
    // T1 = Wk @ S
    sgemm_k<false, false, false, false><<<dim3(8, 4, NB), 128>>>(
        Wk, 0, pS, (long)DD * DD, pT1, nullptr, nullptr,
        nullptr, 0, nullptr, 0, nullptr, 0, nullptr, 0, 1.0f);
    // P = (T1 @ Wv^T + kv1*bv^T + bk*kv2^T) / sqrt(8)
    sgemm_k<false, true, true, false><<<dim3(8, 4, NB), 128>>>(
        pT1, (long)DD * DD, Wv, 0, pP, nullptr, nullptr,
        pkv1, DD, bv, 0, bk, 0, pkv2, DD, inv_sqrt8);
    softmax_kernel<<<dim3(NB, 4), dim3(64, 4)>>>(bq);
    // Mt[e][d] = (aw^T @ Wq), fp16 hi/lo split epilogue
    sgemm_k<true, false, false, true><<<dim3(8, 4, NB), 128>>>(
        pP, (long)DD * DD, Wq, 0, nullptr, pMth, pMtl,
        nullptr, 0, nullptr, 0, nullptr, 0, nullptr, 0, 1.0f);
    stage3_kernel<<<dim3(64, 2, NB), 256, S3_SMEM>>>(query, out);
}